// round 1
// baseline (speedup 1.0000x reference)
#include <cuda_runtime.h>
#include <math.h>
#include <float.h>

// Problem constants
#define BB 16
#define NN 1000
#define EE 4000
#define DD 256
#define NH 4
#define HD 1024
#define LL 64
#define ACT 128
#define OO 256
#define G3 768

// ---------------- scratch (device globals; no allocation allowed) ----------------
__device__ float g_x[BB*NN*DD];        // node embeddings       [16000,256]
__device__ float g_ea[BB*EE*DD];       // edge embeddings       [64000,256]
__device__ float g_q[BB*NN*HD];        // Q                     [16000,1024]
__device__ float g_kx[BB*NN*HD];       // K(node part)
__device__ float g_vx[BB*NN*HD];       // V(node part)
__device__ float g_hbuf[BB*NN*HD];     // skip, then skip+agg (pre-relu h)
__device__ float g_e[BB*EE*HD];        // edge projection       [64000,1024]
__device__ float g_gr[BB*NN*DD];       // graph_repr            [16000,256]
__device__ float g_alpha[BB*EE*NH];    // per-edge attn logits (CSR order)
__device__ int   g_cnt[BB*NN];
__device__ int   g_off[BB*NN];
__device__ int   g_cur[BB*NN];
__device__ int   g_eord[BB*EE];
__device__ float g_invemb[BB*LL*DD];
__device__ float g_invh[BB*LL*DD];
__device__ float g_gx[BB*LL*G3];
__device__ float g_WhhT[DD*G3];        // [256,768] transposed W_hh
__device__ float g_WihT[DD*G3];        // [256,768] transposed W_ih
__device__ float g_invvec[BB*OO];

// ---------------- simple gathers ----------------
__global__ void gather_rows_k(float* __restrict__ out, const float* __restrict__ emb,
                              const int* __restrict__ idx) {
    int row = blockIdx.x, t = threadIdx.x;
    int tok = idx[row];
    out[(size_t)row*DD + t] = emb[(size_t)tok*DD + t];
}

__global__ void transpose_768x256_k(float* __restrict__ out, const float* __restrict__ in) {
    // in [768,256] -> out [256,768]
    int g = blockIdx.x, j = threadIdx.x;
    out[j*G3 + g] = in[g*DD + j];
}

// ---------------- SGEMM: C[M,N] = act(actA(A[M,K]) @ B[K,N] + bias) ----------------
// M,N multiples of 128; K multiple of 8. 256 threads, 128x128 tile, 8x8 microtile.
template<int ARELU, int CRELU, int HASBIAS>
__global__ void sgemm_k(const float* __restrict__ A, const float* __restrict__ B,
                        const float* __restrict__ bias, float* __restrict__ C,
                        int M, int N, int K) {
    __shared__ float As[8][128];
    __shared__ float Bs[8][128];
    const int t  = threadIdx.x;
    const int tx = t & 15, ty = t >> 4;
    const int bm = blockIdx.y * 128, bn = blockIdx.x * 128;
    const int arow = t >> 1, akq = (t & 1) * 4;
    const int bkk  = t >> 5, bn4 = (t & 31) * 4;
    const float* Ap = A + (size_t)(bm + arow) * K + akq;
    const float* Bp = B + (size_t)bkk * N + bn + bn4;

    float acc[8][8];
#pragma unroll
    for (int i = 0; i < 8; i++)
#pragma unroll
        for (int j = 0; j < 8; j++) acc[i][j] = 0.f;

    for (int k0 = 0; k0 < K; k0 += 8) {
        float4 av = *(const float4*)(Ap + k0);
        if (ARELU) {
            av.x = fmaxf(av.x, 0.f); av.y = fmaxf(av.y, 0.f);
            av.z = fmaxf(av.z, 0.f); av.w = fmaxf(av.w, 0.f);
        }
        As[akq+0][arow] = av.x; As[akq+1][arow] = av.y;
        As[akq+2][arow] = av.z; As[akq+3][arow] = av.w;
        float4 bv = *(const float4*)(Bp + (size_t)k0 * N);
        *(float4*)&Bs[bkk][bn4] = bv;
        __syncthreads();
#pragma unroll
        for (int kk = 0; kk < 8; kk++) {
            float a[8], b[8];
#pragma unroll
            for (int i = 0; i < 8; i++) a[i] = As[kk][ty*8 + i];
#pragma unroll
            for (int j = 0; j < 8; j++) b[j] = Bs[kk][tx*8 + j];
#pragma unroll
            for (int i = 0; i < 8; i++)
#pragma unroll
                for (int j = 0; j < 8; j++) acc[i][j] += a[i] * b[j];
        }
        __syncthreads();
    }

    const int col0 = bn + tx*8;
    float bvv[8];
#pragma unroll
    for (int j = 0; j < 8; j++) bvv[j] = HASBIAS ? bias[col0 + j] : 0.f;
#pragma unroll
    for (int i = 0; i < 8; i++) {
        float v[8];
#pragma unroll
        for (int j = 0; j < 8; j++) {
            float w = acc[i][j] + bvv[j];
            if (CRELU) w = fmaxf(w, 0.f);
            v[j] = w;
        }
        float4* cp = (float4*)(C + (size_t)(bm + ty*8 + i) * N + col0);
        cp[0] = make_float4(v[0], v[1], v[2], v[3]);
        cp[1] = make_float4(v[4], v[5], v[6], v[7]);
    }
}

// ---------------- CSR build over dst ----------------
__global__ void zero_cnt_k() {
    int i = blockIdx.x * blockDim.x + threadIdx.x;
    if (i < BB*NN) g_cnt[i] = 0;
}
__global__ void count_k(const int* __restrict__ ei) {
    int i = blockIdx.x * blockDim.x + threadIdx.x;
    if (i >= BB*EE) return;
    int b = i / EE, e = i % EE;
    int dst = ei[(b*2 + 1)*EE + e];
    atomicAdd(&g_cnt[b*NN + dst], 1);
}
__global__ void scan_k() {
    int b = blockIdx.x;
    if (threadIdx.x == 0) {
        int run = 0;
        for (int n = 0; n < NN; n++) {
            g_off[b*NN + n] = run;
            g_cur[b*NN + n] = run;
            run += g_cnt[b*NN + n];
        }
    }
}
__global__ void fill_k(const int* __restrict__ ei) {
    int i = blockIdx.x * blockDim.x + threadIdx.x;
    if (i >= BB*EE) return;
    int b = i / EE, e = i % EE;
    int dst = ei[(b*2 + 1)*EE + e];
    int pos = atomicAdd(&g_cur[b*NN + dst], 1);
    g_eord[b*EE + pos] = e;
}

// ---------------- attention: block per (b,node), warp per head ----------------
__global__ void attn_k(const int* __restrict__ ei) {
    int bn = blockIdx.x;
    int b = bn / NN, n = bn % NN;
    int h = threadIdx.x >> 5, lane = threadIdx.x & 31;
    int deg = g_cnt[b*NN + n];
    if (deg == 0) return;
    int off = g_off[b*NN + n];
    const float* qp = g_q + (size_t)bn*HD + h*DD;
    float qr[8];
#pragma unroll
    for (int r = 0; r < 8; r++) qr[r] = qp[lane + 32*r];

    float m = -3.0e38f;
    for (int i = 0; i < deg; i++) {
        int e = g_eord[b*EE + off + i];
        int src = ei[(b*2)*EE + e];
        const float* kp = g_kx + (size_t)(b*NN + src)*HD + h*DD;
        const float* ep = g_e  + (size_t)(b*EE + e)*HD + h*DD;
        float acc = 0.f;
#pragma unroll
        for (int r = 0; r < 8; r++) acc += qr[r] * (kp[lane + 32*r] + ep[lane + 32*r]);
#pragma unroll
        for (int d = 16; d; d >>= 1) acc += __shfl_xor_sync(0xffffffffu, acc, d);
        acc *= 0.0625f;  // 1/sqrt(256)
        if (lane == 0) g_alpha[(b*EE + off + i)*NH + h] = acc;
        m = fmaxf(m, acc);
    }
    float s = 0.f;
    for (int i = 0; i < deg; i++)
        s += expf(g_alpha[(b*EE + off + i)*NH + h] - m);
    float inv_s = 1.f / s;

    float o[8];
#pragma unroll
    for (int r = 0; r < 8; r++) o[r] = 0.f;
    for (int i = 0; i < deg; i++) {
        int e = g_eord[b*EE + off + i];
        int src = ei[(b*2)*EE + e];
        float w = expf(g_alpha[(b*EE + off + i)*NH + h] - m) * inv_s;
        const float* vp = g_vx + (size_t)(b*NN + src)*HD + h*DD;
        const float* ep = g_e  + (size_t)(b*EE + e)*HD + h*DD;
#pragma unroll
        for (int r = 0; r < 8; r++) o[r] += w * (vp[lane + 32*r] + ep[lane + 32*r]);
    }
    float* hp = g_hbuf + (size_t)bn*HD + h*DD;
#pragma unroll
    for (int r = 0; r < 8; r++) hp[lane + 32*r] += o[r];  // exclusive owner: no atomics
}

// ---------------- mixed embed for inv sequence ----------------
__global__ void mixed_inv_k(const int* __restrict__ tok, const int* __restrict__ nod,
                            const float* __restrict__ emb) {
    int row = blockIdx.x, t = threadIdx.x;
    int b = row / LL;
    int tk = tok[row], nd = nod[row];
    g_invemb[(size_t)row*DD + t] = emb[(size_t)tk*DD + t] + g_gr[(size_t)(b*NN + nd)*DD + t];
}

// ---------------- GRU: one block per batch, 64 sequential steps ----------------
__global__ void gru_k(const float* __restrict__ b_hh) {
    __shared__ float hs[256];
    __shared__ float ghs[768];
    int b = blockIdx.x, t = threadIdx.x;
    hs[t] = 0.f;
    __syncthreads();
    float4 bh = make_float4(0.f, 0.f, 0.f, 0.f);
    if (t < 192) bh = *(const float4*)(b_hh + 4*t);
    for (int l = 0; l < LL; l++) {
        if (t < 192) {
            float ax = bh.x, ay = bh.y, az = bh.z, aw = bh.w;
#pragma unroll 4
            for (int j = 0; j < 256; j++) {
                float hv = hs[j];
                float4 wv = *(const float4*)(g_WhhT + j*G3 + 4*t);
                ax += hv*wv.x; ay += hv*wv.y; az += hv*wv.z; aw += hv*wv.w;
            }
            *(float4*)(ghs + 4*t) = make_float4(ax, ay, az, aw);
        }
        __syncthreads();
        const float* g = g_gx + (size_t)(b*LL + l)*G3;
        float r = 1.f / (1.f + expf(-(g[t]       + ghs[t])));
        float z = 1.f / (1.f + expf(-(g[256 + t] + ghs[256 + t])));
        float c = tanhf(g[512 + t] + r * ghs[512 + t]);
        float hn = (1.f - z) * c + z * hs[t];
        __syncthreads();
        hs[t] = hn;
        __syncthreads();
    }
    g_invvec[b*OO + t] = hs[t];
}

// ---------------- scoring: block per batch ----------------
__global__ void score_k(const float* __restrict__ Wap, const float* __restrict__ bap,
                        const float* __restrict__ Wab, const float* __restrict__ bab,
                        const int* __restrict__ aa_token, const int* __restrict__ aa_node,
                        const float* __restrict__ mask, const float* __restrict__ emb,
                        float* __restrict__ out) {
    __shared__ float invs[256];
    __shared__ float u[256];
    __shared__ float red[256];
    int b = blockIdx.x, t = threadIdx.x;
    int warp = t >> 5, lane = t & 31;
    invs[t] = g_invvec[b*OO + t];
    __syncthreads();
    // u[d] = sum_o Wap[d,o]*inv[o] + Wab[d]
    for (int d = warp*32; d < warp*32 + 32; d++) {
        float acc = 0.f;
#pragma unroll
        for (int r = 0; r < 8; r++) {
            int o = lane + 32*r;
            acc += Wap[(size_t)d*OO + o] * invs[o];
        }
#pragma unroll
        for (int dd = 16; dd; dd >>= 1) acc += __shfl_xor_sync(0xffffffffu, acc, dd);
        if (lane == 0) u[d] = acc + Wab[d];
    }
    red[t] = bap[t] * invs[t];
    __syncthreads();
    for (int s = 128; s; s >>= 1) {
        if (t < s) red[t] += red[t + s];
        __syncthreads();
    }
    float cb = red[0] + bab[0];
    for (int a = warp; a < ACT; a += 8) {
        int tok = aa_token[b*ACT + a], nod = aa_node[b*ACT + a];
        const float* er = emb + (size_t)tok*DD;
        const float* gg = g_gr + (size_t)(b*NN + nod)*DD;
        float acc = 0.f;
#pragma unroll
        for (int r = 0; r < 8; r++) {
            int d = lane + 32*r;
            acc += (er[d] + gg[d]) * u[d];
        }
#pragma unroll
        for (int dd = 16; dd; dd >>= 1) acc += __shfl_xor_sync(0xffffffffu, acc, dd);
        if (lane == 0) {
            float mk = mask[b*ACT + a];
            float lm = fmaxf(logf(mk), -FLT_MAX);
            out[b*ACT + a] = acc + cb + lm;
        }
    }
}

// ---------------- host launcher ----------------
extern "C" void kernel_launch(void* const* d_in, const int* in_sizes, int n_in,
                              void* d_out, int out_size) {
    const int*   node_tokens = (const int*)d_in[0];
    const int*   edge_tokens = (const int*)d_in[1];
    const int*   edge_index  = (const int*)d_in[2];
    const int*   inv_token   = (const int*)d_in[3];
    const int*   inv_node    = (const int*)d_in[4];
    const int*   aa_token    = (const int*)d_in[5];
    const int*   aa_node     = (const int*)d_in[6];
    const float* action_mask = (const float*)d_in[7];
    const float* emb         = (const float*)d_in[8];
    const float* Wq  = (const float*)d_in[9];
    const float* bq  = (const float*)d_in[10];
    const float* Wk  = (const float*)d_in[11];
    const float* bk  = (const float*)d_in[12];
    const float* Wv  = (const float*)d_in[13];
    const float* bv  = (const float*)d_in[14];
    const float* We  = (const float*)d_in[15];
    const float* Wsk = (const float*)d_in[16];
    const float* bsk = (const float*)d_in[17];
    const float* W1  = (const float*)d_in[18];
    const float* b1  = (const float*)d_in[19];
    const float* Wp  = (const float*)d_in[20];
    const float* bp  = (const float*)d_in[21];
    const float* W_ih = (const float*)d_in[22];
    const float* W_hh = (const float*)d_in[23];
    const float* b_ih = (const float*)d_in[24];
    const float* b_hh = (const float*)d_in[25];
    const float* Wab = (const float*)d_in[26];
    const float* bab = (const float*)d_in[27];
    const float* Wap = (const float*)d_in[28];
    const float* bap = (const float*)d_in[29];
    float* out = (float*)d_out;

    void* p;
    float *x_, *ea_, *q_, *kx_, *vx_, *hbuf_, *e_, *gr_, *invemb_, *invh_, *gx_, *WhhT_, *WihT_;
    cudaGetSymbolAddress(&p, g_x);      x_ = (float*)p;
    cudaGetSymbolAddress(&p, g_ea);     ea_ = (float*)p;
    cudaGetSymbolAddress(&p, g_q);      q_ = (float*)p;
    cudaGetSymbolAddress(&p, g_kx);     kx_ = (float*)p;
    cudaGetSymbolAddress(&p, g_vx);     vx_ = (float*)p;
    cudaGetSymbolAddress(&p, g_hbuf);   hbuf_ = (float*)p;
    cudaGetSymbolAddress(&p, g_e);      e_ = (float*)p;
    cudaGetSymbolAddress(&p, g_gr);     gr_ = (float*)p;
    cudaGetSymbolAddress(&p, g_invemb); invemb_ = (float*)p;
    cudaGetSymbolAddress(&p, g_invh);   invh_ = (float*)p;
    cudaGetSymbolAddress(&p, g_gx);     gx_ = (float*)p;
    cudaGetSymbolAddress(&p, g_WhhT);   WhhT_ = (float*)p;
    cudaGetSymbolAddress(&p, g_WihT);   WihT_ = (float*)p;

    // 1. gathers + weight transposes
    gather_rows_k<<<BB*NN, 256>>>(x_, emb, node_tokens);
    gather_rows_k<<<BB*EE, 256>>>(ea_, emb, edge_tokens);
    transpose_768x256_k<<<G3, 256>>>(WhhT_, W_hh);
    transpose_768x256_k<<<G3, 256>>>(WihT_, W_ih);

    // 2. node projections: q/k/v/skip  [16000,256]@[256,1024]
    dim3 gproj(HD/128, (BB*NN)/128);
    sgemm_k<0,0,1><<<gproj, 256>>>(x_, Wq,  bq,  q_,    BB*NN, HD, DD);
    sgemm_k<0,0,1><<<gproj, 256>>>(x_, Wk,  bk,  kx_,   BB*NN, HD, DD);
    sgemm_k<0,0,1><<<gproj, 256>>>(x_, Wv,  bv,  vx_,   BB*NN, HD, DD);
    sgemm_k<0,0,1><<<gproj, 256>>>(x_, Wsk, bsk, hbuf_, BB*NN, HD, DD);

    // 3. edge projection e = ea@We  [64000,256]@[256,1024]
    dim3 gedge(HD/128, (BB*EE)/128);
    sgemm_k<0,0,0><<<gedge, 256>>>(ea_, We, (const float*)nullptr, e_, BB*EE, HD, DD);

    // 4. CSR over dst
    zero_cnt_k<<<(BB*NN + 255)/256, 256>>>();
    count_k<<<(BB*EE + 255)/256, 256>>>(edge_index);
    scan_k<<<BB, 32>>>();
    fill_k<<<(BB*EE + 255)/256, 256>>>(edge_index);

    // 5. attention (adds agg into hbuf which holds skip)
    attn_k<<<BB*NN, 128>>>(edge_index);

    // 6. graph_repr = relu(relu(hbuf)@W1 + b1)  [16000,1024]@[1024,256]
    dim3 ggr(DD/128, (BB*NN)/128);
    sgemm_k<1,1,1><<<ggr, 256>>>(hbuf_, W1, b1, gr_, BB*NN, DD, HD);

    // 7. inv path
    mixed_inv_k<<<BB*LL, 256>>>(inv_token, inv_node, emb);
    dim3 ginv(DD/128, (BB*LL)/128);
    sgemm_k<0,1,1><<<ginv, 256>>>(invemb_, Wp, bp, invh_, BB*LL, DD, DD);
    dim3 ggx(G3/128, (BB*LL)/128);
    sgemm_k<0,0,1><<<ggx, 256>>>(invh_, WihT_, b_ih, gx_, BB*LL, G3, DD);
    gru_k<<<BB, 256>>>(b_hh);

    // 8. scores
    score_k<<<BB, 256>>>(Wap, bap, Wab, bab, aa_token, aa_node, action_mask, emb, out);
    (void)in_sizes; (void)n_in; (void)out_size;
}

// round 3
// speedup vs baseline: 1.8084x; 1.8084x over previous
#include <cuda_runtime.h>
#include <cuda_bf16.h>
#include <math.h>
#include <float.h>
#include <stdint.h>

// Problem constants
#define BB 16
#define NN 1000
#define EE 4000
#define DD 256
#define NH 4
#define HD 1024
#define LL 64
#define ACT 128
#define OO 256
#define G3 768

// ================= scratch (device globals) =================
__device__ __align__(16) float g_x[BB*NN*DD];
__device__ __align__(16) float g_ea[BB*EE*DD];
__device__ __align__(16) float g_q[BB*NN*HD];
__device__ __align__(16) float g_kx[BB*NN*HD];
__device__ __align__(16) float g_vx[BB*NN*HD];
__device__ __align__(16) float g_hbuf[BB*NN*HD];
__device__ __align__(16) float g_e[(size_t)BB*EE*HD];
__device__ __align__(16) float g_gr[BB*NN*DD];
__device__ float g_alpha[BB*EE*NH];
__device__ int   g_cnt[BB*NN];
__device__ int   g_off[BB*NN];
__device__ int   g_cur[BB*NN];
__device__ int   g_eord[BB*EE];
__device__ __align__(16) float g_invemb[BB*LL*DD];
__device__ __align__(16) float g_invh[BB*LL*DD];
__device__ __align__(16) float g_gx[BB*LL*G3];
__device__ __align__(16) float g_WhhT[DD*G3];
__device__ float g_invvec[BB*OO];
// bf16 split weight buffers, [N,K] layout (k contiguous)
__device__ __align__(16) __nv_bfloat16 g_bhi_q[HD*DD],  g_blo_q[HD*DD];
__device__ __align__(16) __nv_bfloat16 g_bhi_k[HD*DD],  g_blo_k[HD*DD];
__device__ __align__(16) __nv_bfloat16 g_bhi_v[HD*DD],  g_blo_v[HD*DD];
__device__ __align__(16) __nv_bfloat16 g_bhi_s[HD*DD],  g_blo_s[HD*DD];
__device__ __align__(16) __nv_bfloat16 g_bhi_e[HD*DD],  g_blo_e[HD*DD];
__device__ __align__(16) __nv_bfloat16 g_bhi_w1[DD*HD], g_blo_w1[DD*HD];
__device__ __align__(16) __nv_bfloat16 g_bhi_wp[DD*DD], g_blo_wp[DD*DD];
__device__ __align__(16) __nv_bfloat16 g_bhi_ih[G3*DD], g_blo_ih[G3*DD];

// ================= helpers =================
__device__ __forceinline__ uint32_t smem_to_u32(const void* smem_ptr) {
    uint32_t addr;
    asm("{ .reg .u64 tmp; cvta.to.shared.u64 tmp, %1; cvt.u32.u64 %0, tmp; }"
        : "=r"(addr) : "l"(smem_ptr));
    return addr;
}
__device__ __forceinline__ void ldsm4(uint32_t r[4], uint32_t addr) {
    asm volatile("ldmatrix.sync.aligned.m8n8.x4.shared.b16 {%0,%1,%2,%3}, [%4];"
        : "=r"(r[0]), "=r"(r[1]), "=r"(r[2]), "=r"(r[3]) : "r"(addr));
}
__device__ __forceinline__ void mma16816(float c[4], uint32_t a0, uint32_t a1,
                                         uint32_t a2, uint32_t a3,
                                         uint32_t b0, uint32_t b1) {
    asm volatile(
        "mma.sync.aligned.m16n8k16.row.col.f32.bf16.bf16.f32 "
        "{%0,%1,%2,%3}, {%4,%5,%6,%7}, {%8,%9}, {%0,%1,%2,%3};"
        : "+f"(c[0]), "+f"(c[1]), "+f"(c[2]), "+f"(c[3])
        : "r"(a0), "r"(a1), "r"(a2), "r"(a3), "r"(b0), "r"(b1));
}

// ================= gathers / conversions =================
__global__ void gather_rows_k(float* __restrict__ out, const float* __restrict__ emb,
                              const int* __restrict__ idx) {
    int row = blockIdx.x, t = threadIdx.x;
    int tok = idx[row];
    out[(size_t)row*DD + t] = emb[(size_t)tok*DD + t];
}
__global__ void transpose_768x256_k(float* __restrict__ out, const float* __restrict__ in) {
    int g = blockIdx.x, j = threadIdx.x;
    out[j*G3 + g] = in[g*DD + j];
}
// W[K,N] fp32 -> Bhi/Blo [N,K] bf16
__global__ void convWT_k(const float* __restrict__ W, __nv_bfloat16* __restrict__ bhi,
                         __nv_bfloat16* __restrict__ blo, int K, int N) {
    int k = blockIdx.x;
    for (int n = threadIdx.x; n < N; n += blockDim.x) {
        float f = W[(size_t)k*N + n];
        __nv_bfloat16 h = __float2bfloat16_rn(f);
        float fl = f - __bfloat162float(h);
        bhi[(size_t)n*K + k] = h;
        blo[(size_t)n*K + k] = __float2bfloat16_rn(fl);
    }
}
__global__ void convWN_k(const float* __restrict__ W, __nv_bfloat16* __restrict__ bhi,
                         __nv_bfloat16* __restrict__ blo, int total) {
    int i = blockIdx.x * blockDim.x + threadIdx.x;
    if (i >= total) return;
    float f = W[i];
    __nv_bfloat16 h = __float2bfloat16_rn(f);
    bhi[i] = h;
    blo[i] = __float2bfloat16_rn(f - __bfloat162float(h));
}

// ================= mma.sync bf16x3 GEMM =================
// C[M,N] = act(actA(A[M,K]) @ B^T + bias), A fp32 [M,K] row-major, B split bf16 [N,K].
// CTA tile 128x128, 8 warps (2x4), warp tile 64x32. K chunk 32. Padded smem rows (40 bf16).
#define KC 32
#define RSB 80            // smem row stride in bytes (40 bf16)
#define ST_A_HI 0
#define ST_A_LO 10240
#define ST_B_HI 20480
#define ST_B_LO 30720
#define STAGE_SZ 40960
#define GEMM_SMEM (2*STAGE_SZ)

template<int ARELU, int CRELU, int HASBIAS>
__global__ __launch_bounds__(256, 1) void mmagemm_k(
    const float* __restrict__ A, const __nv_bfloat16* __restrict__ Bhi,
    const __nv_bfloat16* __restrict__ Blo, const float* __restrict__ bias,
    float* __restrict__ C, int Nld, int K) {
    extern __shared__ char smc[];
    const uint32_t smb = smem_to_u32(smc);
    const int t = threadIdx.x, lane = t & 31, warp = t >> 5;
    const int bm = blockIdx.y * 128, bn = blockIdx.x * 128;
    const int wm = (warp >> 2) * 64, wn = (warp & 3) * 32;

    // fill indexing: thread covers row fr, 16 k-elems starting at fk
    const int fr = t >> 1, fk = (t & 1) * 16;
    const float* Ap = A + (size_t)(bm + fr) * K + fk;
    const __nv_bfloat16* Bhp = Bhi + (size_t)(bn + fr) * K + fk;
    const __nv_bfloat16* Blp = Blo + (size_t)(bn + fr) * K + fk;
    char* fillBase = smc + fr * RSB + fk * 2;

    // ldmatrix per-thread base offsets
    const uint32_t aBase = smb + (uint32_t)(wm + (lane & 15)) * RSB + (uint32_t)(lane >> 4) * 16;
    const uint32_t bBase = smb + (uint32_t)(wn + ((lane >> 4) << 3) + (lane & 7)) * RSB
                               + (uint32_t)((lane >> 3) & 1) * 16;

    float acc[4][4][4];
#pragma unroll
    for (int i = 0; i < 4; i++)
#pragma unroll
        for (int j = 0; j < 4; j++)
#pragma unroll
            for (int k = 0; k < 4; k++) acc[i][j][k] = 0.f;

    const int NC = K / KC;
    float4 fa[4];
    uint4 pbh[2], pbl[2];

    // prologue load chunk 0
    {
        const float* ap = Ap;
#pragma unroll
        for (int j = 0; j < 4; j++) fa[j] = *(const float4*)(ap + 4*j);
        pbh[0] = *(const uint4*)(Bhp);     pbh[1] = *(const uint4*)(Bhp + 8);
        pbl[0] = *(const uint4*)(Blp);     pbl[1] = *(const uint4*)(Blp + 8);
    }
    // store chunk 0 into stage 0
    {
        float fs[16];
#pragma unroll
        for (int j = 0; j < 4; j++) {
            fs[4*j+0]=fa[j].x; fs[4*j+1]=fa[j].y; fs[4*j+2]=fa[j].z; fs[4*j+3]=fa[j].w;
        }
        if (ARELU) {
#pragma unroll
            for (int j = 0; j < 16; j++) fs[j] = fmaxf(fs[j], 0.f);
        }
        uint32_t hw[8], lw[8];
#pragma unroll
        for (int j = 0; j < 8; j++) {
            float a = fs[2*j], b = fs[2*j+1];
            __nv_bfloat162 hp = __floats2bfloat162_rn(a, b);
            float2 hf = __bfloat1622float2(hp);
            __nv_bfloat162 lp = __floats2bfloat162_rn(a - hf.x, b - hf.y);
            hw[j] = *reinterpret_cast<uint32_t*>(&hp);
            lw[j] = *reinterpret_cast<uint32_t*>(&lp);
        }
        char* b0 = fillBase;
        *(uint4*)(b0 + ST_A_HI)      = make_uint4(hw[0],hw[1],hw[2],hw[3]);
        *(uint4*)(b0 + ST_A_HI + 16) = make_uint4(hw[4],hw[5],hw[6],hw[7]);
        *(uint4*)(b0 + ST_A_LO)      = make_uint4(lw[0],lw[1],lw[2],lw[3]);
        *(uint4*)(b0 + ST_A_LO + 16) = make_uint4(lw[4],lw[5],lw[6],lw[7]);
        *(uint4*)(b0 + ST_B_HI)      = pbh[0];
        *(uint4*)(b0 + ST_B_HI + 16) = pbh[1];
        *(uint4*)(b0 + ST_B_LO)      = pbl[0];
        *(uint4*)(b0 + ST_B_LO + 16) = pbl[1];
    }
    __syncthreads();

    for (int c = 0; c < NC; c++) {
        const int s = c & 1;
        const bool more = (c + 1 < NC);
        if (more) {
            const float* ap = Ap + (c+1) * KC;
#pragma unroll
            for (int j = 0; j < 4; j++) fa[j] = *(const float4*)(ap + 4*j);
            const __nv_bfloat16* bh = Bhp + (c+1) * KC;
            const __nv_bfloat16* bl = Blp + (c+1) * KC;
            pbh[0] = *(const uint4*)(bh); pbh[1] = *(const uint4*)(bh + 8);
            pbl[0] = *(const uint4*)(bl); pbl[1] = *(const uint4*)(bl + 8);
        }

        // ---- compute chunk c from stage s ----
        const uint32_t stg = (uint32_t)(s * STAGE_SZ);
#pragma unroll
        for (int ks = 0; ks < 2; ks++) {         // k16 step: byte offset ks*32
            const uint32_t kb = (uint32_t)(ks * 32);
#pragma unroll
            for (int pass = 0; pass < 3; pass++) {
                const uint32_t selA = (pass == 1) ? ST_A_LO : ST_A_HI;
                const uint32_t selB = (pass == 2) ? ST_B_LO : ST_B_HI;
                uint32_t ar[4][4];
#pragma unroll
                for (int mi = 0; mi < 4; mi++)
                    ldsm4(ar[mi], aBase + stg + selA + (uint32_t)(mi * 16 * RSB) + kb);
                uint32_t br[2][4];
#pragma unroll
                for (int nb = 0; nb < 2; nb++)
                    ldsm4(br[nb], bBase + stg + selB + (uint32_t)(nb * 16 * RSB) + kb);
#pragma unroll
                for (int mi = 0; mi < 4; mi++)
#pragma unroll
                    for (int ni = 0; ni < 4; ni++)
                        mma16816(acc[mi][ni], ar[mi][0], ar[mi][1], ar[mi][2], ar[mi][3],
                                 br[ni>>1][(ni&1)*2], br[ni>>1][(ni&1)*2+1]);
            }
        }

        if (more) {
            float fs[16];
#pragma unroll
            for (int j = 0; j < 4; j++) {
                fs[4*j+0]=fa[j].x; fs[4*j+1]=fa[j].y; fs[4*j+2]=fa[j].z; fs[4*j+3]=fa[j].w;
            }
            if (ARELU) {
#pragma unroll
                for (int j = 0; j < 16; j++) fs[j] = fmaxf(fs[j], 0.f);
            }
            uint32_t hw[8], lw[8];
#pragma unroll
            for (int j = 0; j < 8; j++) {
                float a = fs[2*j], b = fs[2*j+1];
                __nv_bfloat162 hp = __floats2bfloat162_rn(a, b);
                float2 hf = __bfloat1622float2(hp);
                __nv_bfloat162 lp = __floats2bfloat162_rn(a - hf.x, b - hf.y);
                hw[j] = *reinterpret_cast<uint32_t*>(&hp);
                lw[j] = *reinterpret_cast<uint32_t*>(&lp);
            }
            char* b0 = fillBase + (s ^ 1) * STAGE_SZ;
            *(uint4*)(b0 + ST_A_HI)      = make_uint4(hw[0],hw[1],hw[2],hw[3]);
            *(uint4*)(b0 + ST_A_HI + 16) = make_uint4(hw[4],hw[5],hw[6],hw[7]);
            *(uint4*)(b0 + ST_A_LO)      = make_uint4(lw[0],lw[1],lw[2],lw[3]);
            *(uint4*)(b0 + ST_A_LO + 16) = make_uint4(lw[4],lw[5],lw[6],lw[7]);
            *(uint4*)(b0 + ST_B_HI)      = pbh[0];
            *(uint4*)(b0 + ST_B_HI + 16) = pbh[1];
            *(uint4*)(b0 + ST_B_LO)      = pbl[0];
            *(uint4*)(b0 + ST_B_LO + 16) = pbl[1];
        }
        __syncthreads();
    }

    // ---- epilogue ----
#pragma unroll
    for (int mi = 0; mi < 4; mi++) {
        const int r0 = bm + wm + mi*16 + (lane >> 2);
        float* C0 = C + (size_t)r0 * Nld;
        float* C1 = C0 + (size_t)8 * Nld;
#pragma unroll
        for (int ni = 0; ni < 4; ni++) {
            const int col = bn + wn + ni*8 + (lane & 3)*2;
            float bx = 0.f, by = 0.f;
            if (HASBIAS) { bx = bias[col]; by = bias[col+1]; }
            float v0 = acc[mi][ni][0] + bx, v1 = acc[mi][ni][1] + by;
            float v2 = acc[mi][ni][2] + bx, v3 = acc[mi][ni][3] + by;
            if (CRELU) {
                v0 = fmaxf(v0, 0.f); v1 = fmaxf(v1, 0.f);
                v2 = fmaxf(v2, 0.f); v3 = fmaxf(v3, 0.f);
            }
            *(float2*)(C0 + col) = make_float2(v0, v1);
            *(float2*)(C1 + col) = make_float2(v2, v3);
        }
    }
}

// ================= CSR build over dst =================
__global__ void zero_cnt_k() {
    int i = blockIdx.x * blockDim.x + threadIdx.x;
    if (i < BB*NN) g_cnt[i] = 0;
}
__global__ void count_k(const int* __restrict__ ei) {
    int i = blockIdx.x * blockDim.x + threadIdx.x;
    if (i >= BB*EE) return;
    int b = i / EE, e = i % EE;
    int dst = ei[(b*2 + 1)*EE + e];
    atomicAdd(&g_cnt[b*NN + dst], 1);
}
__global__ void scan_k() {
    int b = blockIdx.x;
    if (threadIdx.x == 0) {
        int run = 0;
        for (int n = 0; n < NN; n++) {
            g_off[b*NN + n] = run;
            g_cur[b*NN + n] = run;
            run += g_cnt[b*NN + n];
        }
    }
}
__global__ void fill_k(const int* __restrict__ ei) {
    int i = blockIdx.x * blockDim.x + threadIdx.x;
    if (i >= BB*EE) return;
    int b = i / EE, e = i % EE;
    int dst = ei[(b*2 + 1)*EE + e];
    int pos = atomicAdd(&g_cur[b*NN + dst], 1);
    g_eord[b*EE + pos] = e;
}

// ================= attention =================
__global__ void attn_k(const int* __restrict__ ei) {
    int bn = blockIdx.x;
    int b = bn / NN, n = bn % NN;
    int h = threadIdx.x >> 5, lane = threadIdx.x & 31;
    int deg = g_cnt[b*NN + n];
    if (deg == 0) return;
    int off = g_off[b*NN + n];
    const float* qp = g_q + (size_t)bn*HD + h*DD;
    float qr[8];
#pragma unroll
    for (int r = 0; r < 8; r++) qr[r] = qp[lane + 32*r];

    float m = -3.0e38f;
    for (int i = 0; i < deg; i++) {
        int e = g_eord[b*EE + off + i];
        int src = ei[(b*2)*EE + e];
        const float* kp = g_kx + (size_t)(b*NN + src)*HD + h*DD;
        const float* ep = g_e  + (size_t)(b*EE + e)*HD + h*DD;
        float acc = 0.f;
#pragma unroll
        for (int r = 0; r < 8; r++) acc += qr[r] * (kp[lane + 32*r] + ep[lane + 32*r]);
#pragma unroll
        for (int d = 16; d; d >>= 1) acc += __shfl_xor_sync(0xffffffffu, acc, d);
        acc *= 0.0625f;
        if (lane == 0) g_alpha[(b*EE + off + i)*NH + h] = acc;
        m = fmaxf(m, acc);
    }
    float s = 0.f;
    for (int i = 0; i < deg; i++)
        s += expf(g_alpha[(b*EE + off + i)*NH + h] - m);
    float inv_s = 1.f / s;

    float o[8];
#pragma unroll
    for (int r = 0; r < 8; r++) o[r] = 0.f;
    for (int i = 0; i < deg; i++) {
        int e = g_eord[b*EE + off + i];
        int src = ei[(b*2)*EE + e];
        float w = expf(g_alpha[(b*EE + off + i)*NH + h] - m) * inv_s;
        const float* vp = g_vx + (size_t)(b*NN + src)*HD + h*DD;
        const float* ep = g_e  + (size_t)(b*EE + e)*HD + h*DD;
#pragma unroll
        for (int r = 0; r < 8; r++) o[r] += w * (vp[lane + 32*r] + ep[lane + 32*r]);
    }
    float* hp = g_hbuf + (size_t)bn*HD + h*DD;
#pragma unroll
    for (int r = 0; r < 8; r++) hp[lane + 32*r] += o[r];
}

// ================= inv path =================
__global__ void mixed_inv_k(const int* __restrict__ tok, const int* __restrict__ nod,
                            const float* __restrict__ emb) {
    int row = blockIdx.x, t = threadIdx.x;
    int b = row / LL;
    int tk = tok[row], nd = nod[row];
    g_invemb[(size_t)row*DD + t] = emb[(size_t)tk*DD + t] + g_gr[(size_t)(b*NN + nd)*DD + t];
}

__global__ void gru_k(const float* __restrict__ b_hh) {
    __shared__ float hs[256];
    __shared__ float ghs[768];
    int b = blockIdx.x, t = threadIdx.x;
    if (t < 256) hs[t] = 0.f;
    float bh = b_hh[t];
    __syncthreads();
    for (int l = 0; l < LL; l++) {
        float acc = bh;
        const float* w = g_WhhT + t;
#pragma unroll 8
        for (int j = 0; j < 256; j++) acc += hs[j] * w[(size_t)j * G3];
        ghs[t] = acc;
        __syncthreads();
        float hn = 0.f;
        if (t < 256) {
            const float* g = g_gx + (size_t)(b*LL + l)*G3;
            float r = 1.f / (1.f + expf(-(g[t]       + ghs[t])));
            float z = 1.f / (1.f + expf(-(g[256 + t] + ghs[256 + t])));
            float c = tanhf(g[512 + t] + r * ghs[512 + t]);
            hn = (1.f - z) * c + z * hs[t];
        }
        __syncthreads();
        if (t < 256) hs[t] = hn;
        __syncthreads();
    }
    if (t < 256) g_invvec[b*OO + t] = hs[t];
}

// ================= scoring =================
__global__ void score_k(const float* __restrict__ Wap, const float* __restrict__ bap,
                        const float* __restrict__ Wab, const float* __restrict__ bab,
                        const int* __restrict__ aa_token, const int* __restrict__ aa_node,
                        const float* __restrict__ mask, const float* __restrict__ emb,
                        float* __restrict__ out) {
    __shared__ float invs[256];
    __shared__ float u[256];
    __shared__ float red[256];
    int b = blockIdx.x, t = threadIdx.x;
    int warp = t >> 5, lane = t & 31;
    invs[t] = g_invvec[b*OO + t];
    __syncthreads();
    for (int d = warp*32; d < warp*32 + 32; d++) {
        float acc = 0.f;
#pragma unroll
        for (int r = 0; r < 8; r++) {
            int o = lane + 32*r;
            acc += Wap[(size_t)d*OO + o] * invs[o];
        }
#pragma unroll
        for (int dd = 16; dd; dd >>= 1) acc += __shfl_xor_sync(0xffffffffu, acc, dd);
        if (lane == 0) u[d] = acc + Wab[d];
    }
    red[t] = bap[t] * invs[t];
    __syncthreads();
    for (int s = 128; s; s >>= 1) {
        if (t < s) red[t] += red[t + s];
        __syncthreads();
    }
    float cb = red[0] + bab[0];
    for (int a = warp; a < ACT; a += 8) {
        int tok = aa_token[b*ACT + a], nod = aa_node[b*ACT + a];
        const float* er = emb + (size_t)tok*DD;
        const float* gg = g_gr + (size_t)(b*NN + nod)*DD;
        float acc = 0.f;
#pragma unroll
        for (int r = 0; r < 8; r++) {
            int d = lane + 32*r;
            acc += (er[d] + gg[d]) * u[d];
        }
#pragma unroll
        for (int dd = 16; dd; dd >>= 1) acc += __shfl_xor_sync(0xffffffffu, acc, dd);
        if (lane == 0) {
            float mk = mask[b*ACT + a];
            float lm = fmaxf(logf(mk), -FLT_MAX);
            out[b*ACT + a] = acc + cb + lm;
        }
    }
}

// ================= host launcher =================
extern "C" void kernel_launch(void* const* d_in, const int* in_sizes, int n_in,
                              void* d_out, int out_size) {
    const int*   node_tokens = (const int*)d_in[0];
    const int*   edge_tokens = (const int*)d_in[1];
    const int*   edge_index  = (const int*)d_in[2];
    const int*   inv_token   = (const int*)d_in[3];
    const int*   inv_node    = (const int*)d_in[4];
    const int*   aa_token    = (const int*)d_in[5];
    const int*   aa_node     = (const int*)d_in[6];
    const float* action_mask = (const float*)d_in[7];
    const float* emb         = (const float*)d_in[8];
    const float* Wq  = (const float*)d_in[9];
    const float* bq  = (const float*)d_in[10];
    const float* Wk  = (const float*)d_in[11];
    const float* bk  = (const float*)d_in[12];
    const float* Wv  = (const float*)d_in[13];
    const float* bv  = (const float*)d_in[14];
    const float* We  = (const float*)d_in[15];
    const float* Wsk = (const float*)d_in[16];
    const float* bsk = (const float*)d_in[17];
    const float* W1  = (const float*)d_in[18];
    const float* b1  = (const float*)d_in[19];
    const float* Wp  = (const float*)d_in[20];
    const float* bp  = (const float*)d_in[21];
    const float* W_ih = (const float*)d_in[22];
    const float* W_hh = (const float*)d_in[23];
    const float* b_ih = (const float*)d_in[24];
    const float* b_hh = (const float*)d_in[25];
    const float* Wab = (const float*)d_in[26];
    const float* bab = (const float*)d_in[27];
    const float* Wap = (const float*)d_in[28];
    const float* bap = (const float*)d_in[29];
    float* out = (float*)d_out;

    void* p;
    float *x_, *ea_, *q_, *kx_, *vx_, *hbuf_, *e_, *gr_, *invemb_, *invh_, *gx_, *WhhT_;
    cudaGetSymbolAddress(&p, g_x);      x_ = (float*)p;
    cudaGetSymbolAddress(&p, g_ea);     ea_ = (float*)p;
    cudaGetSymbolAddress(&p, g_q);      q_ = (float*)p;
    cudaGetSymbolAddress(&p, g_kx);     kx_ = (float*)p;
    cudaGetSymbolAddress(&p, g_vx);     vx_ = (float*)p;
    cudaGetSymbolAddress(&p, g_hbuf);   hbuf_ = (float*)p;
    cudaGetSymbolAddress(&p, g_e);      e_ = (float*)p;
    cudaGetSymbolAddress(&p, g_gr);     gr_ = (float*)p;
    cudaGetSymbolAddress(&p, g_invemb); invemb_ = (float*)p;
    cudaGetSymbolAddress(&p, g_invh);   invh_ = (float*)p;
    cudaGetSymbolAddress(&p, g_gx);     gx_ = (float*)p;
    cudaGetSymbolAddress(&p, g_WhhT);   WhhT_ = (float*)p;

    __nv_bfloat16 *bhq, *blq, *bhk, *blk, *bhv, *blv, *bhs, *bls, *bhe, *ble;
    __nv_bfloat16 *bh1, *bl1, *bhp, *blp, *bhi, *bli;
    cudaGetSymbolAddress(&p, g_bhi_q);  bhq = (__nv_bfloat16*)p;
    cudaGetSymbolAddress(&p, g_blo_q);  blq = (__nv_bfloat16*)p;
    cudaGetSymbolAddress(&p, g_bhi_k);  bhk = (__nv_bfloat16*)p;
    cudaGetSymbolAddress(&p, g_blo_k);  blk = (__nv_bfloat16*)p;
    cudaGetSymbolAddress(&p, g_bhi_v);  bhv = (__nv_bfloat16*)p;
    cudaGetSymbolAddress(&p, g_blo_v);  blv = (__nv_bfloat16*)p;
    cudaGetSymbolAddress(&p, g_bhi_s);  bhs = (__nv_bfloat16*)p;
    cudaGetSymbolAddress(&p, g_blo_s);  bls = (__nv_bfloat16*)p;
    cudaGetSymbolAddress(&p, g_bhi_e);  bhe = (__nv_bfloat16*)p;
    cudaGetSymbolAddress(&p, g_blo_e);  ble = (__nv_bfloat16*)p;
    cudaGetSymbolAddress(&p, g_bhi_w1); bh1 = (__nv_bfloat16*)p;
    cudaGetSymbolAddress(&p, g_blo_w1); bl1 = (__nv_bfloat16*)p;
    cudaGetSymbolAddress(&p, g_bhi_wp); bhp = (__nv_bfloat16*)p;
    cudaGetSymbolAddress(&p, g_blo_wp); blp = (__nv_bfloat16*)p;
    cudaGetSymbolAddress(&p, g_bhi_ih); bhi = (__nv_bfloat16*)p;
    cudaGetSymbolAddress(&p, g_blo_ih); bli = (__nv_bfloat16*)p;

    cudaFuncSetAttribute(mmagemm_k<0,0,1>, cudaFuncAttributeMaxDynamicSharedMemorySize, GEMM_SMEM);
    cudaFuncSetAttribute(mmagemm_k<0,0,0>, cudaFuncAttributeMaxDynamicSharedMemorySize, GEMM_SMEM);
    cudaFuncSetAttribute(mmagemm_k<1,1,1>, cudaFuncAttributeMaxDynamicSharedMemorySize, GEMM_SMEM);
    cudaFuncSetAttribute(mmagemm_k<0,1,1>, cudaFuncAttributeMaxDynamicSharedMemorySize, GEMM_SMEM);

    // 1. gathers + weight prep
    gather_rows_k<<<BB*NN, 256>>>(x_, emb, node_tokens);
    gather_rows_k<<<BB*EE, 256>>>(ea_, emb, edge_tokens);
    transpose_768x256_k<<<G3, 256>>>(WhhT_, W_hh);
    convWT_k<<<DD, 256>>>(Wq,  bhq, blq, DD, HD);
    convWT_k<<<DD, 256>>>(Wk,  bhk, blk, DD, HD);
    convWT_k<<<DD, 256>>>(Wv,  bhv, blv, DD, HD);
    convWT_k<<<DD, 256>>>(Wsk, bhs, bls, DD, HD);
    convWT_k<<<DD, 256>>>(We,  bhe, ble, DD, HD);
    convWT_k<<<HD, 256>>>(W1,  bh1, bl1, HD, DD);
    convWT_k<<<DD, 256>>>(Wp,  bhp, blp, DD, DD);
    convWN_k<<<(G3*DD + 255)/256, 256>>>(W_ih, bhi, bli, G3*DD);

    // 2. node projections: [16000,256] @ [256,1024]
    dim3 gproj(HD/128, (BB*NN)/128);
    mmagemm_k<0,0,1><<<gproj, 256, GEMM_SMEM>>>(x_, bhq, blq, bq,  q_,    HD, DD);
    mmagemm_k<0,0,1><<<gproj, 256, GEMM_SMEM>>>(x_, bhk, blk, bk,  kx_,   HD, DD);
    mmagemm_k<0,0,1><<<gproj, 256, GEMM_SMEM>>>(x_, bhv, blv, bv,  vx_,   HD, DD);
    mmagemm_k<0,0,1><<<gproj, 256, GEMM_SMEM>>>(x_, bhs, bls, bsk, hbuf_, HD, DD);

    // 3. edge projection: [64000,256] @ [256,1024]
    dim3 gedge(HD/128, (BB*EE)/128);
    mmagemm_k<0,0,0><<<gedge, 256, GEMM_SMEM>>>(ea_, bhe, ble, bq /*unused*/, e_, HD, DD);

    // 4. CSR over dst
    zero_cnt_k<<<(BB*NN + 255)/256, 256>>>();
    count_k<<<(BB*EE + 255)/256, 256>>>(edge_index);
    scan_k<<<BB, 32>>>();
    fill_k<<<(BB*EE + 255)/256, 256>>>(edge_index);

    // 5. attention (adds agg into hbuf which holds skip)
    attn_k<<<BB*NN, 128>>>(edge_index);

    // 6. graph_repr = relu(relu(hbuf)@W1 + b1): [16000,1024]@[1024,256]
    dim3 ggr(DD/128, (BB*NN)/128);
    mmagemm_k<1,1,1><<<ggr, 256, GEMM_SMEM>>>(hbuf_, bh1, bl1, b1, gr_, DD, HD);

    // 7. inv path
    mixed_inv_k<<<BB*LL, 256>>>(inv_token, inv_node, emb);
    dim3 ginv(DD/128, (BB*LL)/128);
    mmagemm_k<0,1,1><<<ginv, 256, GEMM_SMEM>>>(invemb_, bhp, blp, bp, invh_, DD, DD);
    dim3 ggx(G3/128, (BB*LL)/128);
    mmagemm_k<0,0,1><<<ggx, 256, GEMM_SMEM>>>(invh_, bhi, bli, b_ih, gx_, G3, DD);
    gru_k<<<BB, 768>>>(b_hh);

    // 8. scores
    score_k<<<BB, 256>>>(Wap, bap, Wab, bab, aa_token, aa_node, action_mask, emb, out);
    (void)in_sizes; (void)n_in; (void)out_size;
}